// round 8
// baseline (speedup 1.0000x reference)
#include <cuda_runtime.h>
#include <math.h>
#include <stdint.h>

#define TT 128
#define BB 128
#define HH 256
#define HID 512
#define KTAG 60
#define START_TAG 58
#define STOP_TAG 59
#define NEGV (-10000.0f)
#define MROWS (TT*BB)   /* 16384 */

typedef unsigned long long ull;

// ---------------- scratch (device globals; no allocation allowed) -------------
__device__ float g_xw[(size_t)2*128*1024*128];  // [d][t][n][b]  (134 MB)
__device__ float g_x[(size_t)MROWS*HID];        // layer input
__device__ float g_curA[(size_t)MROWS*HID];     // relu ping
__device__ float g_curB[(size_t)MROWS*HID];     // relu pong
__device__ float g_outb[(size_t)MROWS*HID];     // bilstm output [t][b][512]
__device__ float g_ht0[2*HH*BB];                // h state ping  [d][h][b]
__device__ float g_ht1[2*HH*BB];                // h state pong
__device__ float g_ct[2*HH*BB];                 // c state init  [d][h][b]
__device__ float g_feats[(size_t)MROWS*64];     // [t][b][64]
__device__ unsigned g_bar;                      // inter-block barrier counter

// ---------------- f32x2 helpers ----------------------------------------------
__device__ __forceinline__ ull pack2(float a, float b) {
    ull r; asm("mov.b64 %0, {%1, %2};" : "=l"(r) : "f"(a), "f"(b)); return r;
}
__device__ __forceinline__ float2 unpack2(ull v) {
    float2 r; asm("mov.b64 {%0, %1}, %2;" : "=f"(r.x), "=f"(r.y) : "l"(v)); return r;
}
__device__ __forceinline__ void fma2(ull& d, ull a, ull b) {
    asm("fma.rn.f32x2 %0, %1, %2, %0;" : "+l"(d) : "l"(a), "l"(b));
}
__device__ __forceinline__ float sigm(float x) {
    float e = __expf(-x);
    float r; asm("rcp.approx.f32 %0, %1;" : "=f"(r) : "f"(1.f + e));
    return r;
}
__device__ __forceinline__ float tanh_(float x) {
    float y; asm("tanh.approx.f32 %0, %1;" : "=f"(y) : "f"(x)); return y;
}
__device__ __forceinline__ void cpa16(uint32_t s, const void* g) {
    asm volatile("cp.async.cg.shared.global [%0], [%1], 16;" :: "r"(s), "l"(g));
}
__device__ __forceinline__ void cpa_commit() {
    asm volatile("cp.async.commit_group;");
}

// ---------------- layer-1 input projection (K=3) ------------------------------
__global__ void xw_l1_kernel(const float* __restrict__ x,
                             const float* __restrict__ W,
                             const float* __restrict__ bias,
                             float* __restrict__ XW)
{
    size_t idx = (size_t)blockIdx.x * 256 + threadIdx.x;
    if (idx >= (size_t)2*128*1024*128) return;
    int b = (int)(idx & 127);
    int g = (int)((idx >> 7) & 1023);
    int t = (int)((idx >> 17) & 127);
    int d = (int)(idx >> 24);
    int n = d*1024 + g;
    const float* xr = x + ((size_t)t*128 + b)*3;
    const float* wr = W + (size_t)n*3;
    XW[idx] = xr[0]*wr[0] + xr[1]*wr[1] + xr[2]*wr[2] + bias[n];
}

// ---------------- big input projection GEMM (f32x2 / FFMA2) -------------------
// X: [16384][512], W: [2048][512]. Tile 128m x 128n, 256 thr, 8x8 microtile
// as 4 m-pairs x 8 n packed fma2. W duplicated (w,w) in smem for direct LDS.64.
__global__ __launch_bounds__(256) void sgemm_xw_kernel(
    const float* __restrict__ A, const float* __restrict__ W,
    const float* __restrict__ bias, float* __restrict__ XW)
{
    __shared__ float  As[16][128];    // 8 KB
    __shared__ float2 Bs[16][128];    // 16 KB, duplicated W
    const int tid  = threadIdx.x;
    const int tIdx = blockIdx.y;      // t (m0 = t*128)
    const int n0   = blockIdx.x * 128;
    const int m0   = tIdx * 128;
    const int tm   = tid & 15;        // m pairs at 2*tm + 32*i
    const int tn   = tid >> 4;        // n = n0 + tn*8 + j

    ull acc[4][8];
#pragma unroll
    for (int i = 0; i < 4; i++)
#pragma unroll
        for (int j = 0; j < 8; j++) acc[i][j] = 0ull;

    for (int k0 = 0; k0 < 512; k0 += 16) {
#pragma unroll
        for (int s = 0; s < 2; s++) {
            int slot = tid + s*256;               // 512 float4 slots
            int r = slot >> 2, c4 = slot & 3;
            float4 v = *(const float4*)(A + (size_t)(m0 + r)*512 + k0 + c4*4);
            As[c4*4+0][r] = v.x; As[c4*4+1][r] = v.y;
            As[c4*4+2][r] = v.z; As[c4*4+3][r] = v.w;
        }
#pragma unroll
        for (int s = 0; s < 2; s++) {
            int slot = tid + s*256;
            int r = slot >> 2, c4 = slot & 3;
            float4 v = *(const float4*)(W + (size_t)(n0 + r)*512 + k0 + c4*4);
            Bs[c4*4+0][r] = make_float2(v.x, v.x);
            Bs[c4*4+1][r] = make_float2(v.y, v.y);
            Bs[c4*4+2][r] = make_float2(v.z, v.z);
            Bs[c4*4+3][r] = make_float2(v.w, v.w);
        }
        __syncthreads();
#pragma unroll
        for (int kk = 0; kk < 16; kk++) {
            ull a[4], b[8];
#pragma unroll
            for (int i = 0; i < 4; i++)
                a[i] = *(const ull*)&As[kk][2*tm + 32*i];
            const ull* brow = (const ull*)&Bs[kk][0];
#pragma unroll
            for (int j = 0; j < 8; j++)
                b[j] = brow[tn*8 + j];
#pragma unroll
            for (int i = 0; i < 4; i++)
#pragma unroll
                for (int j = 0; j < 8; j++)
                    fma2(acc[i][j], a[i], b[j]);
        }
        __syncthreads();
    }

#pragma unroll
    for (int j = 0; j < 8; j++) {
        int n = n0 + tn*8 + j;
        int d = n >> 10, g = n & 1023;
        float bs = bias[n];
        float* dst = XW + ((size_t)(d*128 + tIdx)*1024 + g)*128;
#pragma unroll
        for (int i = 0; i < 4; i++) {
            float2 r = unpack2(acc[i][j]);
            r.x += bs; r.y += bs;
            *(float2*)(dst + 2*tm + 32*i) = r;
        }
    }
}

// ---------------- per-layer state init + barrier reset ------------------------
__global__ void init_state_kernel(const float* __restrict__ h0l,
                                  const float* __restrict__ c0l,
                                  float* __restrict__ ht, float* __restrict__ ct,
                                  unsigned* __restrict__ bar)
{
    if (blockIdx.x == 0 && threadIdx.x == 0) *bar = 0u;
    int idx = blockIdx.x * 256 + threadIdx.x;
    if (idx >= 2*HH*BB) return;
    int b = idx & 127;
    int h = (idx >> 7) & 255;
    int d = idx >> 15;
    ht[idx] = h0l[((size_t)d*BB + b)*HH + h];
    ct[idx] = c0l[((size_t)d*BB + b)*HH + h];
}

// ---------------- persistent BiLSTM layer kernel ------------------------------
__global__ __launch_bounds__(128, 1) void lstm_layer_kernel(
    const float* __restrict__ XW,    // [d][t][1024][128]
    const float* __restrict__ Whh,   // [2][1024][256]
    const float* __restrict__ c0t,   // [d][256][128]
    float* __restrict__ hPing,       // [d][256][128] (holds initial h)
    float* __restrict__ hPong,
    float* __restrict__ out,         // [t][128][512]
    unsigned* __restrict__ bar)
{
    extern __shared__ float sm[];
    float2* Wd  = (float2*)sm;             // 4096 float2
    float4* Wd4 = (float4*)sm;
    float2* hb[2];
    hb[0] = (float2*)(sm + 8192);
    hb[1] = (float2*)(sm + 8192 + 8192);

    const int bx   = blockIdx.x;
    const int d    = bx >> 6;
    const int hc0  = (bx & 63) * 4;
    const int tid  = threadIdx.x;
    const int bps  = tid & 31;
    const int hsel = tid >> 5;
    const int hcol = hc0 + hsel;

    const float* Wg = Whh + (size_t)d*1024*256;
    for (int i = tid; i < 4*4*256; i += 128) {
        int k = i & 255; int g = (i >> 8) & 3; int hc = i >> 10;
        float w = Wg[((size_t)g*256 + hc0 + hc)*256 + k];
        Wd[((size_t)hc*4 + g)*256 + k] = make_float2(w, w);
    }

    const float* cbase = c0t + (size_t)d*(HH*BB) + hcol*128;
    float2 c0v = *(const float2*)(cbase + 2*bps);
    float2 c1v = *(const float2*)(cbase + 64 + 2*bps);
    __syncthreads();

    const uint32_t sb0 = (uint32_t)__cvta_generic_to_shared(hb[0]);
    const uint32_t sb1 = (uint32_t)__cvta_generic_to_shared(hb[1]);

    for (int s = 0; s < 128; s++) {
        const int t = d ? (127 - s) : s;
        const float* hin  = ((s & 1) ? hPong : hPing) + (size_t)d*(HH*BB);
        float*       hout = ((s & 1) ? hPing : hPong) + (size_t)d*(HH*BB);

#pragma unroll
        for (int j = 0; j < 16; j++)
            cpa16(sb0 + (tid + j*128)*16, (const char*)hin + (tid + j*128)*16);
        cpa_commit();
#pragma unroll
        for (int j = 0; j < 16; j++)
            cpa16(sb1 + (tid + j*128)*16, (const char*)(hin + 8192) + (tid + j*128)*16);
        cpa_commit();

        const float* xwb = XW + ((size_t)(d*128 + t)*1024 + hcol)*128;
        ull acc[4][2];
#pragma unroll
        for (int g = 0; g < 4; g++) {
            float2 x0 = *(const float2*)(xwb + (size_t)g*256*128 + 2*bps);
            float2 x1 = *(const float2*)(xwb + (size_t)g*256*128 + 64 + 2*bps);
            acc[g][0] = pack2(x0.x, x0.y);
            acc[g][1] = pack2(x1.x, x1.y);
        }

        for (int c = 0; c < 4; c++) {
            if (c == 3) asm volatile("cp.async.wait_group 0;");
            else        asm volatile("cp.async.wait_group 1;");
            __syncthreads();
            const float2* hbL = hb[c & 1];
            const int kwoff = c * 32;
#pragma unroll 8
            for (int k2 = 0; k2 < 32; k2++) {
                float2 ha0 = hbL[(2*k2)*64 + bps];
                float2 ha1 = hbL[(2*k2)*64 + 32 + bps];
                float2 hb0_ = hbL[(2*k2+1)*64 + bps];
                float2 hb1_ = hbL[(2*k2+1)*64 + 32 + bps];
                ull H00 = pack2(ha0.x, ha0.y);
                ull H01 = pack2(ha1.x, ha1.y);
                ull H10 = pack2(hb0_.x, hb0_.y);
                ull H11 = pack2(hb1_.x, hb1_.y);
#pragma unroll
                for (int g = 0; g < 4; g++) {
                    float4 w4 = Wd4[((size_t)hsel*4 + g)*128 + kwoff + k2];
                    ull W0 = pack2(w4.x, w4.y);
                    ull W1 = pack2(w4.z, w4.w);
                    fma2(acc[g][0], H00, W0);
                    fma2(acc[g][1], H01, W0);
                    fma2(acc[g][0], H10, W1);
                    fma2(acc[g][1], H11, W1);
                }
            }
            if (c + 2 < 4) {
                __syncthreads();
                const uint32_t dst = (c & 1) ? sb1 : sb0;
                const char* src = (const char*)(hin + (size_t)(c+2)*8192);
#pragma unroll
                for (int j = 0; j < 16; j++)
                    cpa16(dst + (tid + j*128)*16, src + (tid + j*128)*16);
                cpa_commit();
            }
        }

        float2 hres0, hres1;
        {
            float2 iv = unpack2(acc[0][0]), fv = unpack2(acc[1][0]);
            float2 gv = unpack2(acc[2][0]), ov = unpack2(acc[3][0]);
            c0v.x = sigm(fv.x)*c0v.x + sigm(iv.x)*tanh_(gv.x);
            c0v.y = sigm(fv.y)*c0v.y + sigm(iv.y)*tanh_(gv.y);
            hres0.x = sigm(ov.x)*tanh_(c0v.x);
            hres0.y = sigm(ov.y)*tanh_(c0v.y);
        }
        {
            float2 iv = unpack2(acc[0][1]), fv = unpack2(acc[1][1]);
            float2 gv = unpack2(acc[2][1]), ov = unpack2(acc[3][1]);
            c1v.x = sigm(fv.x)*c1v.x + sigm(iv.x)*tanh_(gv.x);
            c1v.y = sigm(fv.y)*c1v.y + sigm(iv.y)*tanh_(gv.y);
            hres1.x = sigm(ov.x)*tanh_(c1v.x);
            hres1.y = sigm(ov.y)*tanh_(c1v.y);
        }
        *(float2*)(hout + hcol*128 + 2*bps)      = hres0;
        *(float2*)(hout + hcol*128 + 64 + 2*bps) = hres1;
        {
            float* ob = out + ((size_t)t*128)*512 + d*256 + hcol;
            ob[(2*bps)*512]        = hres0.x;
            ob[(2*bps+1)*512]      = hres0.y;
            ob[(2*bps+64)*512]     = hres1.x;
            ob[(2*bps+65)*512]     = hres1.y;
        }

        if (s == 127) break;

        // ---- inter-block barrier (bounded spin: never hangs the container) ----
        __syncthreads();
        if (tid == 0) {
            __threadfence();
            atomicAdd(bar, 1u);
            const unsigned tgt = 128u * (unsigned)(s + 1);
            unsigned v;
            unsigned tries = 0;
            do {
                asm volatile("ld.global.cg.u32 %0, [%1];" : "=r"(v) : "l"(bar));
                if (v >= tgt) break;
                __nanosleep(64);
            } while (++tries < (1u << 22));   // ~0.5s worst case, then bail
            __threadfence();
        }
        __syncthreads();
    }
}

// ---------------- relu + residual between layers ------------------------------
__global__ void post_relu_kernel(const float* __restrict__ outb,
                                 const float* __restrict__ curOld,
                                 float* __restrict__ x,
                                 float* __restrict__ curNew,
                                 int addPrev)
{
    int idx = blockIdx.x * 256 + threadIdx.x;
    if (idx >= MROWS*HID/4) return;
    float4 o = ((const float4*)outb)[idx];
    float4 r;
    r.x = fmaxf(o.x, 0.f); r.y = fmaxf(o.y, 0.f);
    r.z = fmaxf(o.z, 0.f); r.w = fmaxf(o.w, 0.f);
    float4 xv = r;
    if (addPrev) {
        float4 p = ((const float4*)curOld)[idx];
        xv.x += p.x; xv.y += p.y; xv.z += p.z; xv.w += p.w;
    }
    ((float4*)x)[idx] = xv;
    ((float4*)curNew)[idx] = r;
}

// ---------------- final FC ----------------------------------------------------
__global__ __launch_bounds__(256) void feats_kernel(
    const float* __restrict__ X,
    const float* __restrict__ fcw,
    const float* __restrict__ fcb,
    float* __restrict__ F)
{
    __shared__ float xs[4][512];
    int tid = threadIdx.x;
    int m0 = blockIdx.x * 4;
#pragma unroll
    for (int sI = 0; sI < 2; sI++) {
        int slot = tid + sI*256;
        int r = slot >> 7, c4 = slot & 127;
        *(float4*)&xs[r][c4*4] = *(const float4*)(X + (size_t)(m0 + r)*512 + c4*4);
    }
    __syncthreads();
    int ty = tid >> 6;
    int k = tid & 63;
    if (k < KTAG) {
        const float4* wr = (const float4*)(fcw + (size_t)k*512);
        const float4* xr = (const float4*)&xs[ty][0];
        float acc = 0.f;
#pragma unroll 16
        for (int i = 0; i < 128; i++) {
            float4 w = wr[i]; float4 xv = xr[i];
            acc += w.x*xv.x + w.y*xv.y + w.z*xv.z + w.w*xv.w;
        }
        F[(size_t)(m0 + ty)*64 + k] = acc + fcb[k];
    }
}

// ---------------- CRF NLL -----------------------------------------------------
__global__ __launch_bounds__(64) void crf_kernel(
    const float* __restrict__ F,
    const float* __restrict__ trans,
    const int* __restrict__ tags,
    float* __restrict__ nll)
{
    const int b = blockIdx.x;
    const int tid = threadIdx.x;
    __shared__ float tr[KTAG][KTAG];
    __shared__ float alpha[KTAG];
    __shared__ float red[64];
    for (int i = tid; i < KTAG*KTAG; i += 64) tr[i/KTAG][i%KTAG] = trans[i];
    if (tid < KTAG) alpha[tid] = (tid == START_TAG) ? 0.f : NEGV;
    __syncthreads();
    for (int t = 0; t < TT; t++) {
        float nv = 0.f;
        if (tid < KTAG) {
            float mx = -3.4e38f;
            for (int i = 0; i < KTAG; i++) mx = fmaxf(mx, alpha[i] + tr[tid][i]);
            float s = 0.f;
            for (int i = 0; i < KTAG; i++) s += expf(alpha[i] + tr[tid][i] - mx);
            nv = mx + logf(s) + F[((size_t)t*128 + b)*64 + tid];
        }
        __syncthreads();
        if (tid < KTAG) alpha[tid] = nv;
        __syncthreads();
    }
    float v = (tid < KTAG) ? (alpha[tid] + tr[STOP_TAG][tid]) : -3.4e38f;
    red[tid] = v;
    __syncthreads();
#pragma unroll
    for (int off = 32; off >= 1; off >>= 1) {
        if (tid < off) red[tid] = fmaxf(red[tid], red[tid + off]);
        __syncthreads();
    }
    float mx = red[0];
    __syncthreads();
    red[tid] = (tid < KTAG) ? expf(v - mx) : 0.f;
    __syncthreads();
#pragma unroll
    for (int off = 32; off >= 1; off >>= 1) {
        if (tid < off) red[tid] += red[tid + off];
        __syncthreads();
    }
    float logz = mx + logf(red[0]);
    __syncthreads();
    float gsum = 0.f;
    for (int t = tid; t < TT; t += 64) {
        int tg = tags[t*128 + b];
        int pv = (t == 0) ? START_TAG : tags[(t-1)*128 + b];
        gsum += F[((size_t)t*128 + b)*64 + tg] + tr[tg][pv];
    }
    red[tid] = gsum;
    __syncthreads();
#pragma unroll
    for (int off = 32; off >= 1; off >>= 1) {
        if (tid < off) red[tid] += red[tid + off];
        __syncthreads();
    }
    if (tid == 0) {
        float gold = red[0] + tr[STOP_TAG][tags[127*128 + b]];
        nll[b] = logz - gold;
    }
}

// ---------------- host orchestration ------------------------------------------
#define LSTM_SMEM (3*8192*4)   /* 96 KB dynamic smem */

extern "C" void kernel_launch(void* const* d_in, const int* in_sizes, int n_in,
                              void* d_out, int out_size)
{
    const float* sentence = (const float*)d_in[0];
    const int*   tags     = (const int*)  d_in[1];
    const float* w_ih1    = (const float*)d_in[2];
    const float* w_hh1    = (const float*)d_in[3];
    const float* b1       = (const float*)d_in[4];
    const float* w_ih     = (const float*)d_in[5];
    const float* w_hh     = (const float*)d_in[6];
    const float* bvec     = (const float*)d_in[7];
    const float* fc_w     = (const float*)d_in[8];
    const float* fc_b     = (const float*)d_in[9];
    const float* h0       = (const float*)d_in[10];
    const float* c0       = (const float*)d_in[11];
    const float* trans    = (const float*)d_in[12];
    float* outp = (float*)d_out;

    float *xw, *x, *curA, *curB, *outb, *ht0, *ht1, *ct, *feats;
    unsigned* barp;
    cudaGetSymbolAddress((void**)&xw,    g_xw);
    cudaGetSymbolAddress((void**)&x,     g_x);
    cudaGetSymbolAddress((void**)&curA,  g_curA);
    cudaGetSymbolAddress((void**)&curB,  g_curB);
    cudaGetSymbolAddress((void**)&outb,  g_outb);
    cudaGetSymbolAddress((void**)&ht0,   g_ht0);
    cudaGetSymbolAddress((void**)&ht1,   g_ht1);
    cudaGetSymbolAddress((void**)&ct,    g_ct);
    cudaGetSymbolAddress((void**)&feats, g_feats);
    cudaGetSymbolAddress((void**)&barp,  g_bar);

    cudaFuncSetAttribute(lstm_layer_kernel,
                         cudaFuncAttributeMaxDynamicSharedMemorySize, LSTM_SMEM);

    // ---- layer 1 ----
    xw_l1_kernel<<<131072, 256>>>(sentence, w_ih1, b1, xw);
    init_state_kernel<<<256, 256>>>(h0, c0, ht0, ct, barp);
    lstm_layer_kernel<<<128, 128, LSTM_SMEM>>>(xw, w_hh1, ct, ht0, ht1, outb, barp);
    post_relu_kernel<<<(MROWS*HID/4 + 255)/256, 256>>>(outb, curA, x, curA, 0);

    float* cur = curA;
    float* oth = curB;
    // ---- layers 2..7 ----
    for (int l = 0; l < 6; l++) {
        sgemm_xw_kernel<<<dim3(16, 128), 256>>>(
            x, w_ih + (size_t)l*2*1024*512, bvec + (size_t)l*2048, xw);
        init_state_kernel<<<256, 256>>>(
            h0 + (size_t)(l+1)*2*BB*HH, c0 + (size_t)(l+1)*2*BB*HH, ht0, ct, barp);
        lstm_layer_kernel<<<128, 128, LSTM_SMEM>>>(
            xw, w_hh + (size_t)l*2*1024*256, ct, ht0, ht1, outb, barp);
        if (l < 5) {
            post_relu_kernel<<<(MROWS*HID/4 + 255)/256, 256>>>(outb, cur, x, oth, 1);
            float* tmp = cur; cur = oth; oth = tmp;
        }
    }

    // ---- FC + CRF ----
    feats_kernel<<<4096, 256>>>(outb, fc_w, fc_b, feats);
    crf_kernel<<<128, 64>>>(feats, trans, tags, outp);
}

// round 10
// speedup vs baseline: 1.0090x; 1.0090x over previous
#include <cuda_runtime.h>
#include <math.h>
#include <stdint.h>

#define TT 128
#define BB 128
#define HH 256
#define HID 512
#define KTAG 60
#define START_TAG 58
#define STOP_TAG 59
#define NEGV (-10000.0f)
#define MROWS (TT*BB)   /* 16384 */

typedef unsigned long long ull;

// ---------------- scratch (device globals; no allocation allowed) -------------
__device__ float g_xw[(size_t)2*128*1024*128];  // [d][t][n][b]  (134 MB)
__device__ float g_x[(size_t)MROWS*HID];        // layer input
__device__ float g_curA[(size_t)MROWS*HID];     // relu ping
__device__ float g_curB[(size_t)MROWS*HID];     // relu pong
__device__ float g_outb[(size_t)MROWS*HID];     // bilstm output [t][b][512]
__device__ float g_ht0[2*HH*BB];                // h state ping  [d][h][b]
__device__ float g_ht1[2*HH*BB];                // h state pong
__device__ float g_ct[2*HH*BB];                 // c state init  [d][h][b]
__device__ float g_feats[(size_t)MROWS*64];     // [t][b][64]
__device__ unsigned g_bar[2];                   // per-direction barrier counters

// ---------------- f32x2 helpers ----------------------------------------------
__device__ __forceinline__ ull pack2(float a, float b) {
    ull r; asm("mov.b64 %0, {%1, %2};" : "=l"(r) : "f"(a), "f"(b)); return r;
}
__device__ __forceinline__ float2 unpack2(ull v) {
    float2 r; asm("mov.b64 {%0, %1}, %2;" : "=f"(r.x), "=f"(r.y) : "l"(v)); return r;
}
__device__ __forceinline__ void fma2(ull& d, ull a, ull b) {
    asm("fma.rn.f32x2 %0, %1, %2, %0;" : "+l"(d) : "l"(a), "l"(b));
}
__device__ __forceinline__ float sigm(float x) {
    float e = __expf(-x);
    float r; asm("rcp.approx.f32 %0, %1;" : "=f"(r) : "f"(1.f + e));
    return r;
}
__device__ __forceinline__ float tanh_(float x) {
    float y; asm("tanh.approx.f32 %0, %1;" : "=f"(y) : "f"(x)); return y;
}
__device__ __forceinline__ void cpa16(uint32_t s, const void* g) {
    asm volatile("cp.async.cg.shared.global [%0], [%1], 16;" :: "r"(s), "l"(g));
}
__device__ __forceinline__ void cpa_commit() {
    asm volatile("cp.async.commit_group;");
}

// ---------------- layer-1 input projection (K=3), split in halves -------------
__global__ void xw_l1_kernel(const float* __restrict__ x,
                             const float* __restrict__ W,
                             const float* __restrict__ bias,
                             float* __restrict__ XW, int half)
{
    size_t idx = (size_t)half*16777216ull + (size_t)blockIdx.x * 256 + threadIdx.x;
    if (idx >= (size_t)2*128*1024*128) return;
    int b = (int)(idx & 127);
    int g = (int)((idx >> 7) & 1023);
    int t = (int)((idx >> 17) & 127);
    int d = (int)(idx >> 24);
    int n = d*1024 + g;
    const float* xr = x + ((size_t)t*128 + b)*3;
    const float* wr = W + (size_t)n*3;
    XW[idx] = xr[0]*wr[0] + xr[1]*wr[1] + xr[2]*wr[2] + bias[n];
}

// ---------------- big input projection GEMM (f32x2 / FFMA2) -------------------
__global__ __launch_bounds__(256) void sgemm_xw_kernel(
    const float* __restrict__ A, const float* __restrict__ W,
    const float* __restrict__ bias, float* __restrict__ XW)
{
    __shared__ float  As[16][128];    // 8 KB
    __shared__ float2 Bs[16][128];    // 16 KB, duplicated W
    const int tid  = threadIdx.x;
    const int tIdx = blockIdx.y;      // t (m0 = t*128)
    const int n0   = blockIdx.x * 128;
    const int m0   = tIdx * 128;
    const int tm   = tid & 15;        // m pairs at 2*tm + 32*i
    const int tn   = tid >> 4;        // n = n0 + tn*8 + j

    ull acc[4][8];
#pragma unroll
    for (int i = 0; i < 4; i++)
#pragma unroll
        for (int j = 0; j < 8; j++) acc[i][j] = 0ull;

    for (int k0 = 0; k0 < 512; k0 += 16) {
#pragma unroll
        for (int s = 0; s < 2; s++) {
            int slot = tid + s*256;               // 512 float4 slots
            int r = slot >> 2, c4 = slot & 3;
            float4 v = *(const float4*)(A + (size_t)(m0 + r)*512 + k0 + c4*4);
            As[c4*4+0][r] = v.x; As[c4*4+1][r] = v.y;
            As[c4*4+2][r] = v.z; As[c4*4+3][r] = v.w;
        }
#pragma unroll
        for (int s = 0; s < 2; s++) {
            int slot = tid + s*256;
            int r = slot >> 2, c4 = slot & 3;
            float4 v = *(const float4*)(W + (size_t)(n0 + r)*512 + k0 + c4*4);
            Bs[c4*4+0][r] = make_float2(v.x, v.x);
            Bs[c4*4+1][r] = make_float2(v.y, v.y);
            Bs[c4*4+2][r] = make_float2(v.z, v.z);
            Bs[c4*4+3][r] = make_float2(v.w, v.w);
        }
        __syncthreads();
#pragma unroll
        for (int kk = 0; kk < 16; kk++) {
            ull a[4], b[8];
#pragma unroll
            for (int i = 0; i < 4; i++)
                a[i] = *(const ull*)&As[kk][2*tm + 32*i];
            const ull* brow = (const ull*)&Bs[kk][0];
#pragma unroll
            for (int j = 0; j < 8; j++)
                b[j] = brow[tn*8 + j];
#pragma unroll
            for (int i = 0; i < 4; i++)
#pragma unroll
                for (int j = 0; j < 8; j++)
                    fma2(acc[i][j], a[i], b[j]);
        }
        __syncthreads();
    }

#pragma unroll
    for (int j = 0; j < 8; j++) {
        int n = n0 + tn*8 + j;
        int d = n >> 10, g = n & 1023;
        float bs = bias[n];
        float* dst = XW + ((size_t)(d*128 + tIdx)*1024 + g)*128;
#pragma unroll
        for (int i = 0; i < 4; i++) {
            float2 r = unpack2(acc[i][j]);
            r.x += bs; r.y += bs;
            *(float2*)(dst + 2*tm + 32*i) = r;
        }
    }
}

// ---------------- per-layer state init + barrier reset ------------------------
__global__ void init_state_kernel(const float* __restrict__ h0l,
                                  const float* __restrict__ c0l,
                                  float* __restrict__ ht, float* __restrict__ ct,
                                  unsigned* __restrict__ bar)
{
    if (blockIdx.x == 0 && threadIdx.x == 0) { bar[0] = 0u; bar[1] = 0u; }
    int idx = blockIdx.x * 256 + threadIdx.x;
    if (idx >= 2*HH*BB) return;
    int b = idx & 127;
    int h = (idx >> 7) & 255;
    int d = idx >> 15;
    ht[idx] = h0l[((size_t)d*BB + b)*HH + h];
    ct[idx] = c0l[((size_t)d*BB + b)*HH + h];
}

// ---------------- persistent BiLSTM layer kernel ------------------------------
// grid 128 = 2 dirs x 64 hcol-tiles (4 hcols). Per-direction inter-block
// barrier; out-scatter + next-step xw prefetch overlapped with barrier wait.
__global__ __launch_bounds__(128, 1) void lstm_layer_kernel(
    const float* __restrict__ XW,    // [d][t][1024][128]
    const float* __restrict__ Whh,   // [2][1024][256]
    const float* __restrict__ c0t,   // [d][256][128]
    float* __restrict__ hPing,       // [d][256][128] (holds initial h)
    float* __restrict__ hPong,
    float* __restrict__ out,         // [t][128][512]
    unsigned* __restrict__ bar)
{
    extern __shared__ float sm[];
    float2* Wd  = (float2*)sm;             // 4096 float2
    float4* Wd4 = (float4*)sm;
    float2* hb[2];
    hb[0] = (float2*)(sm + 8192);
    hb[1] = (float2*)(sm + 8192 + 8192);

    const int bx   = blockIdx.x;
    const int d    = bx >> 6;
    const int hc0  = (bx & 63) * 4;
    const int tid  = threadIdx.x;
    const int bps  = tid & 31;
    const int hsel = tid >> 5;
    const int hcol = hc0 + hsel;

    const float* Wg = Whh + (size_t)d*1024*256;
    for (int i = tid; i < 4*4*256; i += 128) {
        int k = i & 255; int g = (i >> 8) & 3; int hc = i >> 10;
        float w = Wg[((size_t)g*256 + hc0 + hc)*256 + k];
        Wd[((size_t)hc*4 + g)*256 + k] = make_float2(w, w);
    }

    const float* cbase = c0t + (size_t)d*(HH*BB) + hcol*128;
    float2 c0v = *(const float2*)(cbase + 2*bps);
    float2 c1v = *(const float2*)(cbase + 64 + 2*bps);
    __syncthreads();

    const uint32_t sb0 = (uint32_t)__cvta_generic_to_shared(hb[0]);
    const uint32_t sb1 = (uint32_t)__cvta_generic_to_shared(hb[1]);

    // prefetch xw for step 0
    float2 xpre[4][2];
    {
        const int t0 = d ? 127 : 0;
        const float* xwb = XW + ((size_t)(d*128 + t0)*1024 + hcol)*128;
#pragma unroll
        for (int g = 0; g < 4; g++) {
            xpre[g][0] = *(const float2*)(xwb + (size_t)g*256*128 + 2*bps);
            xpre[g][1] = *(const float2*)(xwb + (size_t)g*256*128 + 64 + 2*bps);
        }
    }

    for (int s = 0; s < 128; s++) {
        const int t = d ? (127 - s) : s;
        const float* hin  = ((s & 1) ? hPong : hPing) + (size_t)d*(HH*BB);
        float*       hout = ((s & 1) ? hPing : hPong) + (size_t)d*(HH*BB);

#pragma unroll
        for (int j = 0; j < 16; j++)
            cpa16(sb0 + (tid + j*128)*16, (const char*)hin + (tid + j*128)*16);
        cpa_commit();
#pragma unroll
        for (int j = 0; j < 16; j++)
            cpa16(sb1 + (tid + j*128)*16, (const char*)(hin + 8192) + (tid + j*128)*16);
        cpa_commit();

        // init accumulators from prefetched xw (includes bias)
        ull acc[4][2];
#pragma unroll
        for (int g = 0; g < 4; g++) {
            acc[g][0] = pack2(xpre[g][0].x, xpre[g][0].y);
            acc[g][1] = pack2(xpre[g][1].x, xpre[g][1].y);
        }

        for (int c = 0; c < 4; c++) {
            if (c == 3) asm volatile("cp.async.wait_group 0;");
            else        asm volatile("cp.async.wait_group 1;");
            __syncthreads();
            const float2* hbL = hb[c & 1];
            const int kwoff = c * 32;
#pragma unroll 8
            for (int k2 = 0; k2 < 32; k2++) {
                float2 ha0 = hbL[(2*k2)*64 + bps];
                float2 ha1 = hbL[(2*k2)*64 + 32 + bps];
                float2 hb0_ = hbL[(2*k2+1)*64 + bps];
                float2 hb1_ = hbL[(2*k2+1)*64 + 32 + bps];
                ull H00 = pack2(ha0.x, ha0.y);
                ull H01 = pack2(ha1.x, ha1.y);
                ull H10 = pack2(hb0_.x, hb0_.y);
                ull H11 = pack2(hb1_.x, hb1_.y);
#pragma unroll
                for (int g = 0; g < 4; g++) {
                    float4 w4 = Wd4[((size_t)hsel*4 + g)*128 + kwoff + k2];
                    ull W0 = pack2(w4.x, w4.y);
                    ull W1 = pack2(w4.z, w4.w);
                    fma2(acc[g][0], H00, W0);
                    fma2(acc[g][1], H01, W0);
                    fma2(acc[g][0], H10, W1);
                    fma2(acc[g][1], H11, W1);
                }
            }
            if (c + 2 < 4) {
                __syncthreads();
                const uint32_t dst = (c & 1) ? sb1 : sb0;
                const char* src = (const char*)(hin + (size_t)(c+2)*8192);
#pragma unroll
                for (int j = 0; j < 16; j++)
                    cpa16(dst + (tid + j*128)*16, src + (tid + j*128)*16);
                cpa_commit();
            }
        }

        float2 hres0, hres1;
        {
            float2 iv = unpack2(acc[0][0]), fv = unpack2(acc[1][0]);
            float2 gv = unpack2(acc[2][0]), ov = unpack2(acc[3][0]);
            c0v.x = sigm(fv.x)*c0v.x + sigm(iv.x)*tanh_(gv.x);
            c0v.y = sigm(fv.y)*c0v.y + sigm(iv.y)*tanh_(gv.y);
            hres0.x = sigm(ov.x)*tanh_(c0v.x);
            hres0.y = sigm(ov.y)*tanh_(c0v.y);
        }
        {
            float2 iv = unpack2(acc[0][1]), fv = unpack2(acc[1][1]);
            float2 gv = unpack2(acc[2][1]), ov = unpack2(acc[3][1]);
            c1v.x = sigm(fv.x)*c1v.x + sigm(iv.x)*tanh_(gv.x);
            c1v.y = sigm(fv.y)*c1v.y + sigm(iv.y)*tanh_(gv.y);
            hres1.x = sigm(ov.x)*tanh_(c1v.x);
            hres1.y = sigm(ov.y)*tanh_(c1v.y);
        }
        // h feedback store (participates in inter-block dependency)
        *(float2*)(hout + hcol*128 + 2*bps)      = hres0;
        *(float2*)(hout + hcol*128 + 64 + 2*bps) = hres1;

        __syncthreads();
        // arrive early (per-direction counter)
        if (s < 127 && tid == 0) {
            __threadfence();
            atomicAdd(&bar[d], 1u);
        }

        // ---- overlapped with barrier wait: out scatter + next xw prefetch ----
        {
            float* ob = out + ((size_t)t*128)*512 + d*256 + hcol;
            ob[(2*bps)*512]        = hres0.x;
            ob[(2*bps+1)*512]      = hres0.y;
            ob[(2*bps+64)*512]     = hres1.x;
            ob[(2*bps+65)*512]     = hres1.y;
        }
        if (s == 127) break;
        {
            const int tn_ = d ? (127 - (s + 1)) : (s + 1);
            const float* xwn = XW + ((size_t)(d*128 + tn_)*1024 + hcol)*128;
#pragma unroll
            for (int g = 0; g < 4; g++) {
                xpre[g][0] = *(const float2*)(xwn + (size_t)g*256*128 + 2*bps);
                xpre[g][1] = *(const float2*)(xwn + (size_t)g*256*128 + 64 + 2*bps);
            }
        }

        // ---- bounded wait on this direction's 64 blocks ----
        if (tid == 0) {
            const unsigned tgt = 64u * (unsigned)(s + 1);
            unsigned v;
            unsigned tries = 0;
            do {
                asm volatile("ld.global.cg.u32 %0, [%1];" : "=r"(v) : "l"(&bar[d]));
                if (v >= tgt) break;
                __nanosleep(64);
            } while (++tries < (1u << 22));
            __threadfence();
        }
        __syncthreads();
    }
}

// ---------------- relu + residual between layers ------------------------------
__global__ void post_relu_kernel(const float* __restrict__ outb,
                                 const float* __restrict__ curOld,
                                 float* __restrict__ x,
                                 float* __restrict__ curNew,
                                 int addPrev)
{
    int idx = blockIdx.x * 256 + threadIdx.x;
    if (idx >= MROWS*HID/4) return;
    float4 o = ((const float4*)outb)[idx];
    float4 r;
    r.x = fmaxf(o.x, 0.f); r.y = fmaxf(o.y, 0.f);
    r.z = fmaxf(o.z, 0.f); r.w = fmaxf(o.w, 0.f);
    float4 xv = r;
    if (addPrev) {
        float4 p = ((const float4*)curOld)[idx];
        xv.x += p.x; xv.y += p.y; xv.z += p.z; xv.w += p.w;
    }
    ((float4*)x)[idx] = xv;
    ((float4*)curNew)[idx] = r;
}

// ---------------- final FC ----------------------------------------------------
__global__ __launch_bounds__(256) void feats_kernel(
    const float* __restrict__ X,
    const float* __restrict__ fcw,
    const float* __restrict__ fcb,
    float* __restrict__ F)
{
    __shared__ float xs[4][512];
    int tid = threadIdx.x;
    int m0 = blockIdx.x * 4;
#pragma unroll
    for (int sI = 0; sI < 2; sI++) {
        int slot = tid + sI*256;
        int r = slot >> 7, c4 = slot & 127;
        *(float4*)&xs[r][c4*4] = *(const float4*)(X + (size_t)(m0 + r)*512 + c4*4);
    }
    __syncthreads();
    int ty = tid >> 6;
    int k = tid & 63;
    if (k < KTAG) {
        const float4* wr = (const float4*)(fcw + (size_t)k*512);
        const float4* xr = (const float4*)&xs[ty][0];
        float acc = 0.f;
#pragma unroll 16
        for (int i = 0; i < 128; i++) {
            float4 w = wr[i]; float4 xv = xr[i];
            acc += w.x*xv.x + w.y*xv.y + w.z*xv.z + w.w*xv.w;
        }
        F[(size_t)(m0 + ty)*64 + k] = acc + fcb[k];
    }
}

// ---------------- CRF NLL -----------------------------------------------------
__global__ __launch_bounds__(64) void crf_kernel(
    const float* __restrict__ F,
    const float* __restrict__ trans,
    const int* __restrict__ tags,
    float* __restrict__ nll)
{
    const int b = blockIdx.x;
    const int tid = threadIdx.x;
    __shared__ float tr[KTAG][KTAG];
    __shared__ float alpha[KTAG];
    __shared__ float red[64];
    for (int i = tid; i < KTAG*KTAG; i += 64) tr[i/KTAG][i%KTAG] = trans[i];
    if (tid < KTAG) alpha[tid] = (tid == START_TAG) ? 0.f : NEGV;
    __syncthreads();
    for (int t = 0; t < TT; t++) {
        float nv = 0.f;
        if (tid < KTAG) {
            float mx = -3.4e38f;
            for (int i = 0; i < KTAG; i++) mx = fmaxf(mx, alpha[i] + tr[tid][i]);
            float s = 0.f;
            for (int i = 0; i < KTAG; i++) s += expf(alpha[i] + tr[tid][i] - mx);
            nv = mx + logf(s) + F[((size_t)t*128 + b)*64 + tid];
        }
        __syncthreads();
        if (tid < KTAG) alpha[tid] = nv;
        __syncthreads();
    }
    float v = (tid < KTAG) ? (alpha[tid] + tr[STOP_TAG][tid]) : -3.4e38f;
    red[tid] = v;
    __syncthreads();
#pragma unroll
    for (int off = 32; off >= 1; off >>= 1) {
        if (tid < off) red[tid] = fmaxf(red[tid], red[tid + off]);
        __syncthreads();
    }
    float mx = red[0];
    __syncthreads();
    red[tid] = (tid < KTAG) ? expf(v - mx) : 0.f;
    __syncthreads();
#pragma unroll
    for (int off = 32; off >= 1; off >>= 1) {
        if (tid < off) red[tid] += red[tid + off];
        __syncthreads();
    }
    float logz = mx + logf(red[0]);
    __syncthreads();
    float gsum = 0.f;
    for (int t = tid; t < TT; t += 64) {
        int tg = tags[t*128 + b];
        int pv = (t == 0) ? START_TAG : tags[(t-1)*128 + b];
        gsum += F[((size_t)t*128 + b)*64 + tg] + tr[tg][pv];
    }
    red[tid] = gsum;
    __syncthreads();
#pragma unroll
    for (int off = 32; off >= 1; off >>= 1) {
        if (tid < off) red[tid] += red[tid + off];
        __syncthreads();
    }
    if (tid == 0) {
        float gold = red[0] + tr[STOP_TAG][tags[127*128 + b]];
        nll[b] = logz - gold;
    }
}

// ---------------- host orchestration ------------------------------------------
#define LSTM_SMEM (3*8192*4)   /* 96 KB dynamic smem */

extern "C" void kernel_launch(void* const* d_in, const int* in_sizes, int n_in,
                              void* d_out, int out_size)
{
    const float* sentence = (const float*)d_in[0];
    const int*   tags     = (const int*)  d_in[1];
    const float* w_ih1    = (const float*)d_in[2];
    const float* w_hh1    = (const float*)d_in[3];
    const float* b1       = (const float*)d_in[4];
    const float* w_ih     = (const float*)d_in[5];
    const float* w_hh     = (const float*)d_in[6];
    const float* bvec     = (const float*)d_in[7];
    const float* fc_w     = (const float*)d_in[8];
    const float* fc_b     = (const float*)d_in[9];
    const float* h0       = (const float*)d_in[10];
    const float* c0       = (const float*)d_in[11];
    const float* trans    = (const float*)d_in[12];
    float* outp = (float*)d_out;

    float *xw, *x, *curA, *curB, *outb, *ht0, *ht1, *ct, *feats;
    unsigned* barp;
    cudaGetSymbolAddress((void**)&xw,    g_xw);
    cudaGetSymbolAddress((void**)&x,     g_x);
    cudaGetSymbolAddress((void**)&curA,  g_curA);
    cudaGetSymbolAddress((void**)&curB,  g_curB);
    cudaGetSymbolAddress((void**)&outb,  g_outb);
    cudaGetSymbolAddress((void**)&ht0,   g_ht0);
    cudaGetSymbolAddress((void**)&ht1,   g_ht1);
    cudaGetSymbolAddress((void**)&ct,    g_ct);
    cudaGetSymbolAddress((void**)&feats, g_feats);
    cudaGetSymbolAddress((void**)&barp,  g_bar);

    cudaFuncSetAttribute(lstm_layer_kernel,
                         cudaFuncAttributeMaxDynamicSharedMemorySize, LSTM_SMEM);

    // ---- layer 1 (order arranged so launch #4 = lstm_layer for ncu) ----
    init_state_kernel<<<256, 256>>>(h0, c0, ht0, ct, barp);
    xw_l1_kernel<<<65536, 256>>>(sentence, w_ih1, b1, xw, 0);
    xw_l1_kernel<<<65536, 256>>>(sentence, w_ih1, b1, xw, 1);
    lstm_layer_kernel<<<128, 128, LSTM_SMEM>>>(xw, w_hh1, ct, ht0, ht1, outb, barp);
    post_relu_kernel<<<(MROWS*HID/4 + 255)/256, 256>>>(outb, curA, x, curA, 0);

    float* cur = curA;
    float* oth = curB;
    // ---- layers 2..7 ----
    for (int l = 0; l < 6; l++) {
        sgemm_xw_kernel<<<dim3(16, 128), 256>>>(
            x, w_ih + (size_t)l*2*1024*512, bvec + (size_t)l*2048, xw);
        init_state_kernel<<<256, 256>>>(
            h0 + (size_t)(l+1)*2*BB*HH, c0 + (size_t)(l+1)*2*BB*HH, ht0, ct, barp);
        lstm_layer_kernel<<<128, 128, LSTM_SMEM>>>(
            xw, w_hh + (size_t)l*2*1024*256, ct, ht0, ht1, outb, barp);
        if (l < 5) {
            post_relu_kernel<<<(MROWS*HID/4 + 255)/256, 256>>>(outb, cur, x, oth, 1);
            float* tmp = cur; cur = oth; oth = tmp;
        }
    }

    // ---- FC + CRF ----
    feats_kernel<<<4096, 256>>>(outb, fc_w, fc_b, feats);
    crf_kernel<<<128, 64>>>(feats, trans, tags, outp);
}